// round 15
// baseline (speedup 1.0000x reference)
#include <cuda_runtime.h>
#include <cuda_bf16.h>
#include <cstdint>

#define HW 65536
#define EPSN 1e-12f

typedef unsigned long long u64;

// ---------------- scratch (static device globals; no allocation) ----------------
__device__ unsigned g_qmb[16777216]; // [8][64][32768] bf16-pair qm
__device__ unsigned g_kvl[16777216]; // [8][64][32768] bf16-pair kvm low (k source)
__device__ float    g_kvh[33554432]; // [8][64][65536] f32 kvm high (v source)
__device__ float    g_v  [33554432]; // [8][64][65536] v after dwconv
__device__ float g_gram[8192];       // [8][4][16][16]
__device__ float g_qss[512];         // [8][64]
__device__ float g_kss[512];         // [8][64]

// ---------------- helpers ----------------
__device__ __forceinline__ float bflo(unsigned u){ return __int_as_float((int)(u << 16)); }
__device__ __forceinline__ float bfhi(unsigned u){ return __int_as_float((int)(u & 0xffff0000u)); }
__device__ __forceinline__ unsigned pkbf(float a, float b){
    __nv_bfloat162 p = __floats2bfloat162_rn(a, b);
    return *(unsigned*)&p;
}
__device__ __forceinline__ float bf16f(float x){
    return __bfloat162float(__float2bfloat16_rn(x));
}

// ---------------- warp mma (arch-generic bf16 HMMA) ----------------
__device__ __forceinline__ void mma16816(float* c, const unsigned* a, const unsigned* b){
    asm volatile("mma.sync.aligned.m16n8k16.row.col.f32.bf16.bf16.f32 "
        "{%0,%1,%2,%3}, {%4,%5,%6,%7}, {%8,%9}, {%0,%1,%2,%3};"
        : "+f"(c[0]), "+f"(c[1]), "+f"(c[2]), "+f"(c[3])
        : "r"(a[0]), "r"(a[1]), "r"(a[2]), "r"(a[3]), "r"(b[0]), "r"(b[1]));
}

#define NTILES 4096   // 128-px tiles over 8 batches x 65536 px
#define ROWW 36       // bf16 smem row stride in 32-bit words (72 bf16, padded)
#define QROW 516      // k2 smem channel-row stride in words (512 + 4 pad)

// ---------------- K1a: q path via mma.sync bf16 + accumulator zeroing ----------------
__global__ void __launch_bounds__(256, 3) k1a_mma(
    const float* __restrict__ dg, const float* __restrict__ xin,
    const float* __restrict__ q1w, const float* __restrict__ q2w)
{
    extern __shared__ unsigned smk[];
    unsigned* sD = smk;
    unsigned* sX = smk + 128*ROWW;
    const int tid = threadIdx.x, wid = tid >> 5, lane = tid & 31;
    const int mb = wid & 3, nh = wid >> 2;
    const int grow = lane >> 2, t = lane & 3;

    // zero gram/qss/kss (k2m launches later in-stream)
    {
        const int idx = blockIdx.x*256 + tid;
        if (idx < 8192) g_gram[idx] = 0.f;
        else if (idx < 8704) g_qss[idx - 8192] = 0.f;
        else if (idx < 9216) g_kss[idx - 8704] = 0.f;
    }

    unsigned aW1[4][4], aW2[4][4];
    {
        const int r0 = mb*16 + grow;
        #pragma unroll
        for (int cc = 0; cc < 4; ++cc){
            const int k0 = cc*16 + t*2;
            aW1[cc][0] = pkbf(__ldg(q1w + r0*64 + k0),       __ldg(q1w + r0*64 + k0 + 1));
            aW1[cc][1] = pkbf(__ldg(q1w + (r0+8)*64 + k0),   __ldg(q1w + (r0+8)*64 + k0 + 1));
            aW1[cc][2] = pkbf(__ldg(q1w + r0*64 + k0 + 8),   __ldg(q1w + r0*64 + k0 + 9));
            aW1[cc][3] = pkbf(__ldg(q1w + (r0+8)*64 + k0+8), __ldg(q1w + (r0+8)*64 + k0 + 9));
            aW2[cc][0] = pkbf(__ldg(q2w + r0*64 + k0),       __ldg(q2w + r0*64 + k0 + 1));
            aW2[cc][1] = pkbf(__ldg(q2w + (r0+8)*64 + k0),   __ldg(q2w + (r0+8)*64 + k0 + 1));
            aW2[cc][2] = pkbf(__ldg(q2w + r0*64 + k0 + 8),   __ldg(q2w + r0*64 + k0 + 9));
            aW2[cc][3] = pkbf(__ldg(q2w + (r0+8)*64 + k0+8), __ldg(q2w + (r0+8)*64 + k0 + 9));
        }
    }

    auto cvt = [&](const float* gsrc, unsigned* sT){
        #pragma unroll
        for (int j = 0; j < 8; ++j){
            const int idx = tid + j*256;
            const int ch = idx & 63;
            const int px0 = (idx >> 6) << 2;
            float4 v = __ldg((const float4*)(gsrc + (size_t)ch*HW + px0));
            float o0 = __shfl_xor_sync(0xffffffffu, v.x, 1);
            float o1 = __shfl_xor_sync(0xffffffffu, v.y, 1);
            float o2 = __shfl_xor_sync(0xffffffffu, v.z, 1);
            float o3 = __shfl_xor_sync(0xffffffffu, v.w, 1);
            const int cp = ch >> 1;
            if (!(ch & 1)){
                sT[(px0    )*ROWW + cp] = pkbf(v.x, o0);
                sT[(px0 + 1)*ROWW + cp] = pkbf(v.y, o1);
            } else {
                sT[(px0 + 2)*ROWW + cp] = pkbf(o2, v.z);
                sT[(px0 + 3)*ROWW + cp] = pkbf(o3, v.w);
            }
        }
    };

    for (int tt = blockIdx.x; tt < NTILES; tt += gridDim.x){
        const int bb = tt >> 9;
        const size_t pxb = (size_t)(tt & 511) << 7;

        cvt(dg  + (size_t)bb*64*HW + pxb, sD);
        cvt(xin + (size_t)bb*64*HW + pxb, sX);
        __syncthreads();

        const int pxw0 = (int)(pxb >> 1);
        #pragma unroll
        for (int nt = 0; nt < 8; ++nt){
            const int nb = nh*64 + nt*8;
            const int nrow = nb + grow;
            float ac1[4] = {0.f, 0.f, 0.f, 0.f};
            float ac2[4] = {0.f, 0.f, 0.f, 0.f};
            #pragma unroll
            for (int cc = 0; cc < 4; ++cc){
                unsigned bD[2], bX[2];
                const int w0 = nrow*ROWW + cc*8 + t;
                bD[0] = sD[w0]; bD[1] = sD[w0 + 4];
                bX[0] = sX[w0]; bX[1] = sX[w0 + 4];
                mma16816(ac1, aW1[cc], bD);
                mma16816(ac2, aW2[cc], bX);
            }
            const int ch = bb*64 + mb*16 + grow;
            const int pxp = pxw0 + (nb >> 1) + t;
            g_qmb[(size_t)ch*32768 + pxp]       = pkbf(ac1[0]*ac2[0], ac1[1]*ac2[1]);
            g_qmb[(size_t)(ch + 8)*32768 + pxp] = pkbf(ac1[2]*ac2[2], ac1[3]*ac2[3]);
        }
        __syncthreads();
    }
}

// ---------------- K1b: kv GEMM via split-bf16 mma (R10/R12 proven) ----------------
__global__ void __launch_bounds__(256, 3) k1b_mma(
    const float* __restrict__ yin, const float* __restrict__ kvw)
{
    extern __shared__ unsigned smk[];
    unsigned* sYh = smk;
    unsigned* sYl = smk + 128*ROWW;
    const int tid = threadIdx.x, wid = tid >> 5, lane = tid & 31;
    const int mb = wid & 3, nh = wid >> 2;
    const int grow = lane >> 2, t = lane & 3;

    unsigned aWk[4][4], aWvh[4][4], aWvl[4][4];
    {
        const int r0 = mb*16 + grow;
        #pragma unroll
        for (int cc = 0; cc < 4; ++cc){
            const int k0 = cc*16 + t*2;
            aWk[cc][0] = pkbf(__ldg(kvw + r0*64 + k0),       __ldg(kvw + r0*64 + k0 + 1));
            aWk[cc][1] = pkbf(__ldg(kvw + (r0+8)*64 + k0),   __ldg(kvw + (r0+8)*64 + k0 + 1));
            aWk[cc][2] = pkbf(__ldg(kvw + r0*64 + k0 + 8),   __ldg(kvw + r0*64 + k0 + 9));
            aWk[cc][3] = pkbf(__ldg(kvw + (r0+8)*64 + k0+8), __ldg(kvw + (r0+8)*64 + k0 + 9));
            const float* vw = kvw + 4096;
            float w00 = __ldg(vw + r0*64 + k0),       w01 = __ldg(vw + r0*64 + k0 + 1);
            float w10 = __ldg(vw + (r0+8)*64 + k0),   w11 = __ldg(vw + (r0+8)*64 + k0 + 1);
            float w20 = __ldg(vw + r0*64 + k0 + 8),   w21 = __ldg(vw + r0*64 + k0 + 9);
            float w30 = __ldg(vw + (r0+8)*64 + k0+8), w31 = __ldg(vw + (r0+8)*64 + k0 + 9);
            aWvh[cc][0] = pkbf(w00, w01); aWvl[cc][0] = pkbf(w00 - bf16f(w00), w01 - bf16f(w01));
            aWvh[cc][1] = pkbf(w10, w11); aWvl[cc][1] = pkbf(w10 - bf16f(w10), w11 - bf16f(w11));
            aWvh[cc][2] = pkbf(w20, w21); aWvl[cc][2] = pkbf(w20 - bf16f(w20), w21 - bf16f(w21));
            aWvh[cc][3] = pkbf(w30, w31); aWvl[cc][3] = pkbf(w30 - bf16f(w30), w31 - bf16f(w31));
        }
    }

    for (int tt = blockIdx.x; tt < NTILES; tt += gridDim.x){
        const int bb = tt >> 9;
        const size_t pxb = (size_t)(tt & 511) << 7;
        const float* gy = yin + (size_t)bb*64*HW + pxb;

        #pragma unroll
        for (int j = 0; j < 8; ++j){
            const int idx = tid + j*256;
            const int ch = idx & 63;
            const int px0 = (idx >> 6) << 2;
            float4 v = __ldg((const float4*)(gy + (size_t)ch*HW + px0));
            float o0 = __shfl_xor_sync(0xffffffffu, v.x, 1);
            float o1 = __shfl_xor_sync(0xffffffffu, v.y, 1);
            float o2 = __shfl_xor_sync(0xffffffffu, v.z, 1);
            float o3 = __shfl_xor_sync(0xffffffffu, v.w, 1);
            const int cp = ch >> 1;
            if (!(ch & 1)){
                float h0 = bf16f(v.x), h1 = bf16f(v.y);
                float p0 = bf16f(o0),  p1 = bf16f(o1);
                sYh[(px0    )*ROWW + cp] = pkbf(h0, p0);
                sYh[(px0 + 1)*ROWW + cp] = pkbf(h1, p1);
                sYl[(px0    )*ROWW + cp] = pkbf(v.x - h0, o0 - p0);
                sYl[(px0 + 1)*ROWW + cp] = pkbf(v.y - h1, o1 - p1);
            } else {
                float h2 = bf16f(v.z), h3 = bf16f(v.w);
                float p2 = bf16f(o2),  p3 = bf16f(o3);
                sYh[(px0 + 2)*ROWW + cp] = pkbf(p2, h2);
                sYh[(px0 + 3)*ROWW + cp] = pkbf(p3, h3);
                sYl[(px0 + 2)*ROWW + cp] = pkbf(o2 - p2, v.z - h2);
                sYl[(px0 + 3)*ROWW + cp] = pkbf(o3 - p3, v.w - h3);
            }
        }
        __syncthreads();

        const int pxw0 = (int)(pxb >> 1);
        #pragma unroll
        for (int nt = 0; nt < 8; ++nt){
            const int nb = nh*64 + nt*8;
            const int nrow = nb + grow;
            float ack[4] = {0.f, 0.f, 0.f, 0.f};
            float acv[4] = {0.f, 0.f, 0.f, 0.f};
            #pragma unroll
            for (int cc = 0; cc < 4; ++cc){
                unsigned bH[2], bL[2];
                const int w0 = nrow*ROWW + cc*8 + t;
                bH[0] = sYh[w0]; bH[1] = sYh[w0 + 4];
                bL[0] = sYl[w0]; bL[1] = sYl[w0 + 4];
                mma16816(ack, aWk[cc],  bH);
                mma16816(acv, aWvh[cc], bH);
                mma16816(acv, aWvh[cc], bL);
                mma16816(acv, aWvl[cc], bH);
            }
            const int ch = bb*64 + mb*16 + grow;
            const int pxp = pxw0 + (nb >> 1) + t;
            g_kvl[(size_t)ch*32768 + pxp]       = pkbf(ack[0], ack[1]);
            g_kvl[(size_t)(ch + 8)*32768 + pxp] = pkbf(ack[2], ack[3]);
            const size_t pxa = pxb + nb + 2*t;
            float2 v01; v01.x = acv[0]; v01.y = acv[1];
            float2 v23; v23.x = acv[2]; v23.y = acv[3];
            *(float2*)(g_kvh + (size_t)ch*HW + pxa)       = v01;
            *(float2*)(g_kvh + (size_t)(ch + 8)*HW + pxa) = v23;
        }
        __syncthreads();
    }
}

// ---------------- K2m: merged q/k dwconv+gram (blocks 0..2047) and v dwconv (2048..6143) ----------------
__global__ void __launch_bounds__(256) k2m(
    const float* __restrict__ qdw, const float* __restrict__ kvdw)
{
    extern __shared__ unsigned smq[];
    const int tid = threadIdx.x, wid = tid >> 5, lane = tid & 31;

    if (blockIdx.x < 2048){
        // ===== q/k dwconv + gram mma (R13 k2qk) =====
        unsigned* sQ = smq;
        unsigned* sK = smq + 16*QROW;
        float* sG = (float*)(smq + 32*QROW);

        const int band = blockIdx.x & 63, h = (blockIdx.x >> 6) & 3, b = blockIdx.x >> 8;
        const int y0 = band*4;
        const int xx = lane << 3;

        #pragma unroll
        for (int jj = 0; jj < 4; ++jj){
            const int job = wid*4 + jj;
            const int kindk = job & 1;
            const int c = job >> 1;
            const int cc = h*16 + c;
            const unsigned* srcb = (kindk ? g_kvl : g_qmb) + (((size_t)(b*64 + cc))*HW >> 1);
            const float* w9 = (kindk ? kvdw : qdw) + cc*9;
            float w[9];
            #pragma unroll
            for (int i = 0; i < 9; ++i) w[i] = __ldg(w9 + i);

            float o[4][8];
            #pragma unroll
            for (int j = 0; j < 4; ++j)
                #pragma unroll
                for (int p = 0; p < 8; ++p) o[j][p] = 0.f;

            #pragma unroll
            for (int i = 0; i < 6; ++i){
                const int ys = y0 - 1 + i;
                const bool yok = (ys >= 0) && (ys <= 255);
                uint4 u = make_uint4(0u,0u,0u,0u);
                if (yok) u = __ldg((const uint4*)(srcb + (ys << 7) + (xx >> 1)));
                float c8[8];
                c8[0]=bflo(u.x); c8[1]=bfhi(u.x); c8[2]=bflo(u.y); c8[3]=bfhi(u.y);
                c8[4]=bflo(u.z); c8[5]=bfhi(u.z); c8[6]=bflo(u.w); c8[7]=bfhi(u.w);
                float lv = __shfl_up_sync(0xffffffffu, c8[7], 1);
                float rv = __shfl_down_sync(0xffffffffu, c8[0], 1);
                if (lane == 0)  lv = 0.f;
                if (lane == 31) rv = 0.f;

                #pragma unroll
                for (int j = 0; j < 4; ++j){
                    const int ky = i - j;
                    if (ky >= 0 && ky < 3){
                        const float wa = w[ky*3], wb = w[ky*3+1], wc = w[ky*3+2];
                        o[j][0] += wa*lv + wb*c8[0] + wc*c8[1];
                        #pragma unroll
                        for (int p = 1; p < 7; ++p)
                            o[j][p] += wa*c8[p-1] + wb*c8[p] + wc*c8[p+1];
                        o[j][7] += wa*c8[6] + wb*c8[7] + wc*rv;
                    }
                }
            }

            float s = 0.f;
            #pragma unroll
            for (int j = 0; j < 4; ++j)
                #pragma unroll
                for (int p = 0; p < 8; ++p) s += o[j][p]*o[j][p];
            #pragma unroll
            for (int off = 16; off; off >>= 1) s += __shfl_xor_sync(0xffffffffu, s, off);
            if (lane == 0)
                atomicAdd((kindk ? g_kss : g_qss) + b*64 + cc, s);

            unsigned* dst = (kindk ? sK : sQ) + c*QROW;
            #pragma unroll
            for (int j = 0; j < 4; ++j){
                uint4 u;
                u.x = pkbf(o[j][0], o[j][1]);
                u.y = pkbf(o[j][2], o[j][3]);
                u.z = pkbf(o[j][4], o[j][5]);
                u.w = pkbf(o[j][6], o[j][7]);
                *(uint4*)(dst + j*128 + lane*4) = u;
            }
        }
        __syncthreads();

        const int grow = lane >> 2, t = lane & 3;
        float c0[4] = {0.f, 0.f, 0.f, 0.f};
        float c1[4] = {0.f, 0.f, 0.f, 0.f};

        #pragma unroll
        for (int it = 0; it < 8; ++it){
            const int wb = wid*64 + it*8;
            unsigned a[4], b0[2], b1[2];
            a[0]  = sQ[grow*QROW      + wb + t];
            a[1]  = sQ[(grow+8)*QROW  + wb + t];
            a[2]  = sQ[grow*QROW      + wb + t + 4];
            a[3]  = sQ[(grow+8)*QROW  + wb + t + 4];
            b0[0] = sK[grow*QROW      + wb + t];
            b0[1] = sK[grow*QROW      + wb + t + 4];
            b1[0] = sK[(grow+8)*QROW  + wb + t];
            b1[1] = sK[(grow+8)*QROW  + wb + t + 4];
            mma16816(c0, a, b0);
            mma16816(c1, a, b1);
        }

        sG[wid*256 + grow*16          + t*2    ] = c0[0];
        sG[wid*256 + grow*16          + t*2 + 1] = c0[1];
        sG[wid*256 + (grow+8)*16      + t*2    ] = c0[2];
        sG[wid*256 + (grow+8)*16      + t*2 + 1] = c0[3];
        sG[wid*256 + grow*16 + 8      + t*2    ] = c1[0];
        sG[wid*256 + grow*16 + 8      + t*2 + 1] = c1[1];
        sG[wid*256 + (grow+8)*16 + 8  + t*2    ] = c1[2];
        sG[wid*256 + (grow+8)*16 + 8  + t*2 + 1] = c1[3];
        __syncthreads();

        float s = 0.f;
        #pragma unroll
        for (int w = 0; w < 8; ++w) s += sG[w*256 + tid];
        atomicAdd(g_gram + (b*4 + h)*256 + tid, s);
    } else {
        // ===== v dwconv (R12 k2v path, no smem) =====
        const int vid = blockIdx.x - 2048;
        const int band = vid & 7, c = (vid >> 3) & 63, b = vid >> 9;
        const float* srcf = g_kvh + ((size_t)(b*64 + c))*HW;
        const float* w9 = kvdw + (64 + c)*9;

        float w[9];
        #pragma unroll
        for (int i = 0; i < 9; ++i) w[i] = __ldg(w9 + i);

        const int rg = tid >> 5;
        const int xx = lane << 3;
        const int y0 = band*32 + rg*4;

        float o[4][8];
        #pragma unroll
        for (int j = 0; j < 4; ++j)
            #pragma unroll
            for (int p = 0; p < 8; ++p) o[j][p] = 0.f;

        #pragma unroll
        for (int i = 0; i < 6; ++i){
            const int ys = y0 - 1 + i;
            const bool yok = (ys >= 0) && (ys <= 255);
            float c8[8];
            float4 a = make_float4(0.f,0.f,0.f,0.f), d = make_float4(0.f,0.f,0.f,0.f);
            if (yok){
                const float* row = srcf + ys*256 + xx;
                a = __ldg((const float4*)row);
                d = __ldg((const float4*)(row + 4));
            }
            c8[0]=a.x; c8[1]=a.y; c8[2]=a.z; c8[3]=a.w;
            c8[4]=d.x; c8[5]=d.y; c8[6]=d.z; c8[7]=d.w;
            float lv = __shfl_up_sync(0xffffffffu, c8[7], 1);
            float rv = __shfl_down_sync(0xffffffffu, c8[0], 1);
            if (lane == 0)  lv = 0.f;
            if (lane == 31) rv = 0.f;

            #pragma unroll
            for (int j = 0; j < 4; ++j){
                const int ky = i - j;
                if (ky >= 0 && ky < 3){
                    const float wa = w[ky*3], wb = w[ky*3+1], wc = w[ky*3+2];
                    o[j][0] += wa*lv + wb*c8[0] + wc*c8[1];
                    #pragma unroll
                    for (int p = 1; p < 7; ++p)
                        o[j][p] += wa*c8[p-1] + wb*c8[p] + wc*c8[p+1];
                    o[j][7] += wa*c8[6] + wb*c8[7] + wc*rv;
                }
            }
        }

        const size_t obase = ((size_t)(b*64 + c))*HW + (size_t)y0*256 + xx;
        #pragma unroll
        for (int j = 0; j < 4; ++j){
            float4 a; a.x=o[j][0]; a.y=o[j][1]; a.z=o[j][2]; a.w=o[j][3];
            float4 d; d.x=o[j][4]; d.y=o[j][5]; d.z=o[j][6]; d.w=o[j][7];
            *(float4*)(g_v + obase + (size_t)j*256)     = a;
            *(float4*)(g_v + obase + (size_t)j*256 + 4) = d;
        }
    }
}

// ---------------- K4: split-bf16 mma; prologue computes M = proj∘softmax (R12 proven) ----------------
__global__ void __launch_bounds__(256, 3) k4_mma(
    float* __restrict__ out,
    const float* __restrict__ pjw, const float* __restrict__ temp)
{
    extern __shared__ unsigned smk[];
    unsigned* sVh = smk;
    unsigned* sVl = smk + 128*ROWW;
    float* sM = (float*)(smk + 2*128*ROWW);
    float* sA = sM + 4096;
    const int tid = threadIdx.x, wid = tid >> 5, lane = tid & 31;
    const int mb = wid & 3, nh = wid >> 2;
    const int grow = lane >> 2, t = lane & 3;
    const int b = blockIdx.x & 7;
    const int sub = blockIdx.x >> 3;
    const int bstride = gridDim.x >> 3;

    if (tid < 64){
        const int h = tid >> 4;
        const float tv = __ldg(temp + h);
        const float inq = tv / fmaxf(sqrtf(g_qss[b*64 + tid]), EPSN);
        const float* gr = g_gram + (b*4 + h)*256 + (tid & 15)*16;
        float l[16]; float mx = -1e30f;
        #pragma unroll
        for (int d = 0; d < 16; ++d){
            l[d] = gr[d] * inq / fmaxf(sqrtf(g_kss[b*64 + h*16 + d]), EPSN);
            mx = fmaxf(mx, l[d]);
        }
        float ssum = 0.f;
        #pragma unroll
        for (int d = 0; d < 16; ++d){ l[d] = __expf(l[d] - mx); ssum += l[d]; }
        const float inv = 1.f / ssum;
        #pragma unroll
        for (int d = 0; d < 16; ++d) sA[tid*16 + d] = l[d] * inv;
    }
    __syncthreads();
    for (int idx = tid; idx < 4096; idx += 256){
        const int o = idx >> 6, cd = idx & 63, h = cd >> 4, d = cd & 15;
        float s = 0.f;
        #pragma unroll
        for (int ci = 0; ci < 16; ++ci)
            s += __ldg(pjw + o*64 + h*16 + ci) * sA[(h*16 + ci)*16 + d];
        sM[idx] = s;
    }
    __syncthreads();

    unsigned aMh[4][4], aMl[4][4];
    {
        const int r0 = mb*16 + grow;
        #pragma unroll
        for (int cc = 0; cc < 4; ++cc){
            const int k0 = cc*16 + t*2;
            float w00 = sM[r0*64 + k0],       w01 = sM[r0*64 + k0 + 1];
            float w10 = sM[(r0+8)*64 + k0],   w11 = sM[(r0+8)*64 + k0 + 1];
            float w20 = sM[r0*64 + k0 + 8],   w21 = sM[r0*64 + k0 + 9];
            float w30 = sM[(r0+8)*64 + k0+8], w31 = sM[(r0+8)*64 + k0 + 9];
            aMh[cc][0] = pkbf(w00, w01); aMl[cc][0] = pkbf(w00 - bf16f(w00), w01 - bf16f(w01));
            aMh[cc][1] = pkbf(w10, w11); aMl[cc][1] = pkbf(w10 - bf16f(w10), w11 - bf16f(w11));
            aMh[cc][2] = pkbf(w20, w21); aMl[cc][2] = pkbf(w20 - bf16f(w20), w21 - bf16f(w21));
            aMh[cc][3] = pkbf(w30, w31); aMl[cc][3] = pkbf(w30 - bf16f(w30), w31 - bf16f(w31));
        }
    }

    for (int tt = sub; tt < 512; tt += bstride){
        const size_t pxb = (size_t)tt << 7;
        const float* gv = g_v + (size_t)b*64*HW + pxb;

        #pragma unroll
        for (int j = 0; j < 8; ++j){
            const int idx = tid + j*256;
            const int ch = idx & 63;
            const int px0 = (idx >> 6) << 2;
            float4 v = __ldg((const float4*)(gv + (size_t)ch*HW + px0));
            float o0 = __shfl_xor_sync(0xffffffffu, v.x, 1);
            float o1 = __shfl_xor_sync(0xffffffffu, v.y, 1);
            float o2 = __shfl_xor_sync(0xffffffffu, v.z, 1);
            float o3 = __shfl_xor_sync(0xffffffffu, v.w, 1);
            const int cp = ch >> 1;
            if (!(ch & 1)){
                float h0 = bf16f(v.x), h1 = bf16f(v.y);
                float p0 = bf16f(o0),  p1 = bf16f(o1);
                sVh[(px0    )*ROWW + cp] = pkbf(h0, p0);
                sVh[(px0 + 1)*ROWW + cp] = pkbf(h1, p1);
                sVl[(px0    )*ROWW + cp] = pkbf(v.x - h0, o0 - p0);
                sVl[(px0 + 1)*ROWW + cp] = pkbf(v.y - h1, o1 - p1);
            } else {
                float h2 = bf16f(v.z), h3 = bf16f(v.w);
                float p2 = bf16f(o2),  p3 = bf16f(o3);
                sVh[(px0 + 2)*ROWW + cp] = pkbf(p2, h2);
                sVh[(px0 + 3)*ROWW + cp] = pkbf(p3, h3);
                sVl[(px0 + 2)*ROWW + cp] = pkbf(o2 - p2, v.z - h2);
                sVl[(px0 + 3)*ROWW + cp] = pkbf(o3 - p3, v.w - h3);
            }
        }
        __syncthreads();

        #pragma unroll
        for (int nt = 0; nt < 8; ++nt){
            const int nb = nh*64 + nt*8;
            const int nrow = nb + grow;
            float acv[4] = {0.f, 0.f, 0.f, 0.f};
            #pragma unroll
            for (int cc = 0; cc < 4; ++cc){
                unsigned bH[2], bL[2];
                const int w0 = nrow*ROWW + cc*8 + t;
                bH[0] = sVh[w0]; bH[1] = sVh[w0 + 4];
                bL[0] = sVl[w0]; bL[1] = sVl[w0 + 4];
                mma16816(acv, aMh[cc], bH);
                mma16816(acv, aMh[cc], bL);
                mma16816(acv, aMl[cc], bH);
            }
            const int ch = b*64 + mb*16 + grow;
            const size_t pxa = pxb + nb + 2*t;
            float2 v01; v01.x = acv[0]; v01.y = acv[1];
            float2 v23; v23.x = acv[2]; v23.y = acv[3];
            *(float2*)(out + (size_t)ch*HW + pxa)       = v01;
            *(float2*)(out + (size_t)(ch + 8)*HW + pxa) = v23;
        }
        __syncthreads();
    }
}

// ---------------- launch ----------------
extern "C" void kernel_launch(void* const* d_in, const int* in_sizes, int n_in,
                              void* d_out, int out_size)
{
    (void)in_sizes; (void)n_in; (void)out_size;
    const float* dg   = (const float*)d_in[0];
    const float* xin  = (const float*)d_in[1];
    const float* yin  = (const float*)d_in[2];
    const float* q1w  = (const float*)d_in[3];
    const float* q2w  = (const float*)d_in[4];
    const float* qdw  = (const float*)d_in[5];
    const float* kvw  = (const float*)d_in[6];
    const float* kvdw = (const float*)d_in[7];
    const float* pjw  = (const float*)d_in[8];
    const float* temp = (const float*)d_in[9];
    float* out = (float*)d_out;

    cudaFuncSetAttribute(k1a_mma, cudaFuncAttributeMaxDynamicSharedMemorySize, 36864);
    cudaFuncSetAttribute(k1b_mma, cudaFuncAttributeMaxDynamicSharedMemorySize, 36864);
    cudaFuncSetAttribute(k2m,     cudaFuncAttributeMaxDynamicSharedMemorySize, 74240);
    cudaFuncSetAttribute(k4_mma,  cudaFuncAttributeMaxDynamicSharedMemorySize, 57344);

    k1a_mma<<<444, 256, 36864>>>(dg, xin, q1w, q2w);
    k1b_mma<<<444, 256, 36864>>>(yin, kvw);
    k2m    <<<6144, 256, 74240>>>(qdw, kvdw);
    k4_mma <<<440, 256, 57344>>>(out, pjw, temp);
}

// round 16
// speedup vs baseline: 1.0105x; 1.0105x over previous
#include <cuda_runtime.h>
#include <cuda_bf16.h>
#include <cstdint>

#define HW 65536
#define EPSN 1e-12f

typedef unsigned long long u64;

// ---------------- scratch (static device globals; no allocation) ----------------
__device__ unsigned g_qmb[16777216]; // [8][64][32768] bf16-pair qm
__device__ unsigned g_kvl[16777216]; // [8][64][32768] bf16-pair kvm low (k source)
__device__ float    g_kvh[33554432]; // [8][64][65536] f32 kvm high (v source)
__device__ float    g_v  [33554432]; // [8][64][65536] v after dwconv
__device__ float g_gram[8192];       // [8][4][16][16]
__device__ float g_qss[512];         // [8][64]
__device__ float g_kss[512];         // [8][64]

// ---------------- helpers ----------------
__device__ __forceinline__ float bflo(unsigned u){ return __int_as_float((int)(u << 16)); }
__device__ __forceinline__ float bfhi(unsigned u){ return __int_as_float((int)(u & 0xffff0000u)); }
__device__ __forceinline__ unsigned pkbf(float a, float b){
    __nv_bfloat162 p = __floats2bfloat162_rn(a, b);
    return *(unsigned*)&p;
}
__device__ __forceinline__ float bf16f(float x){
    return __bfloat162float(__float2bfloat16_rn(x));
}

// ---------------- warp mma (arch-generic bf16 HMMA) ----------------
__device__ __forceinline__ void mma16816(float* c, const unsigned* a, const unsigned* b){
    asm volatile("mma.sync.aligned.m16n8k16.row.col.f32.bf16.bf16.f32 "
        "{%0,%1,%2,%3}, {%4,%5,%6,%7}, {%8,%9}, {%0,%1,%2,%3};"
        : "+f"(c[0]), "+f"(c[1]), "+f"(c[2]), "+f"(c[3])
        : "r"(a[0]), "r"(a[1]), "r"(a[2]), "r"(a[3]), "r"(b[0]), "r"(b[1]));
}

#define NTILES 4096   // 128-px tiles over 8 batches x 65536 px
#define ROWW 36       // bf16 smem row stride in 32-bit words (72 bf16, padded)
#define QROW 516      // k2qk smem channel-row stride in words (512 + 4 pad)

// ---------------- K1a: q path via mma.sync bf16 + accumulator zeroing ----------------
__global__ void __launch_bounds__(256, 3) k1a_mma(
    const float* __restrict__ dg, const float* __restrict__ xin,
    const float* __restrict__ q1w, const float* __restrict__ q2w)
{
    extern __shared__ unsigned smk[];
    unsigned* sD = smk;
    unsigned* sX = smk + 128*ROWW;
    const int tid = threadIdx.x, wid = tid >> 5, lane = tid & 31;
    const int mb = wid & 3, nh = wid >> 2;
    const int grow = lane >> 2, t = lane & 3;

    // zero gram/qss/kss (k2qk launches later in-stream)
    {
        const int idx = blockIdx.x*256 + tid;
        if (idx < 8192) g_gram[idx] = 0.f;
        else if (idx < 8704) g_qss[idx - 8192] = 0.f;
        else if (idx < 9216) g_kss[idx - 8704] = 0.f;
    }

    unsigned aW1[4][4], aW2[4][4];
    {
        const int r0 = mb*16 + grow;
        #pragma unroll
        for (int cc = 0; cc < 4; ++cc){
            const int k0 = cc*16 + t*2;
            aW1[cc][0] = pkbf(__ldg(q1w + r0*64 + k0),       __ldg(q1w + r0*64 + k0 + 1));
            aW1[cc][1] = pkbf(__ldg(q1w + (r0+8)*64 + k0),   __ldg(q1w + (r0+8)*64 + k0 + 1));
            aW1[cc][2] = pkbf(__ldg(q1w + r0*64 + k0 + 8),   __ldg(q1w + r0*64 + k0 + 9));
            aW1[cc][3] = pkbf(__ldg(q1w + (r0+8)*64 + k0+8), __ldg(q1w + (r0+8)*64 + k0 + 9));
            aW2[cc][0] = pkbf(__ldg(q2w + r0*64 + k0),       __ldg(q2w + r0*64 + k0 + 1));
            aW2[cc][1] = pkbf(__ldg(q2w + (r0+8)*64 + k0),   __ldg(q2w + (r0+8)*64 + k0 + 1));
            aW2[cc][2] = pkbf(__ldg(q2w + r0*64 + k0 + 8),   __ldg(q2w + r0*64 + k0 + 9));
            aW2[cc][3] = pkbf(__ldg(q2w + (r0+8)*64 + k0+8), __ldg(q2w + (r0+8)*64 + k0 + 9));
        }
    }

    auto cvt = [&](const float* gsrc, unsigned* sT){
        #pragma unroll
        for (int j = 0; j < 8; ++j){
            const int idx = tid + j*256;
            const int ch = idx & 63;
            const int px0 = (idx >> 6) << 2;
            float4 v = __ldg((const float4*)(gsrc + (size_t)ch*HW + px0));
            float o0 = __shfl_xor_sync(0xffffffffu, v.x, 1);
            float o1 = __shfl_xor_sync(0xffffffffu, v.y, 1);
            float o2 = __shfl_xor_sync(0xffffffffu, v.z, 1);
            float o3 = __shfl_xor_sync(0xffffffffu, v.w, 1);
            const int cp = ch >> 1;
            if (!(ch & 1)){
                sT[(px0    )*ROWW + cp] = pkbf(v.x, o0);
                sT[(px0 + 1)*ROWW + cp] = pkbf(v.y, o1);
            } else {
                sT[(px0 + 2)*ROWW + cp] = pkbf(o2, v.z);
                sT[(px0 + 3)*ROWW + cp] = pkbf(o3, v.w);
            }
        }
    };

    for (int tt = blockIdx.x; tt < NTILES; tt += gridDim.x){
        const int bb = tt >> 9;
        const size_t pxb = (size_t)(tt & 511) << 7;

        cvt(dg  + (size_t)bb*64*HW + pxb, sD);
        cvt(xin + (size_t)bb*64*HW + pxb, sX);
        __syncthreads();

        const int pxw0 = (int)(pxb >> 1);
        #pragma unroll
        for (int nt = 0; nt < 8; ++nt){
            const int nb = nh*64 + nt*8;
            const int nrow = nb + grow;
            float ac1[4] = {0.f, 0.f, 0.f, 0.f};
            float ac2[4] = {0.f, 0.f, 0.f, 0.f};
            #pragma unroll
            for (int cc = 0; cc < 4; ++cc){
                unsigned bD[2], bX[2];
                const int w0 = nrow*ROWW + cc*8 + t;
                bD[0] = sD[w0]; bD[1] = sD[w0 + 4];
                bX[0] = sX[w0]; bX[1] = sX[w0 + 4];
                mma16816(ac1, aW1[cc], bD);
                mma16816(ac2, aW2[cc], bX);
            }
            const int ch = bb*64 + mb*16 + grow;
            const int pxp = pxw0 + (nb >> 1) + t;
            g_qmb[(size_t)ch*32768 + pxp]       = pkbf(ac1[0]*ac2[0], ac1[1]*ac2[1]);
            g_qmb[(size_t)(ch + 8)*32768 + pxp] = pkbf(ac1[2]*ac2[2], ac1[3]*ac2[3]);
        }
        __syncthreads();
    }
}

// ---------------- K1b: kv GEMM via split-bf16 mma (R10/R12 proven) ----------------
__global__ void __launch_bounds__(256, 3) k1b_mma(
    const float* __restrict__ yin, const float* __restrict__ kvw)
{
    extern __shared__ unsigned smk[];
    unsigned* sYh = smk;
    unsigned* sYl = smk + 128*ROWW;
    const int tid = threadIdx.x, wid = tid >> 5, lane = tid & 31;
    const int mb = wid & 3, nh = wid >> 2;
    const int grow = lane >> 2, t = lane & 3;

    unsigned aWk[4][4], aWvh[4][4], aWvl[4][4];
    {
        const int r0 = mb*16 + grow;
        #pragma unroll
        for (int cc = 0; cc < 4; ++cc){
            const int k0 = cc*16 + t*2;
            aWk[cc][0] = pkbf(__ldg(kvw + r0*64 + k0),       __ldg(kvw + r0*64 + k0 + 1));
            aWk[cc][1] = pkbf(__ldg(kvw + (r0+8)*64 + k0),   __ldg(kvw + (r0+8)*64 + k0 + 1));
            aWk[cc][2] = pkbf(__ldg(kvw + r0*64 + k0 + 8),   __ldg(kvw + r0*64 + k0 + 9));
            aWk[cc][3] = pkbf(__ldg(kvw + (r0+8)*64 + k0+8), __ldg(kvw + (r0+8)*64 + k0 + 9));
            const float* vw = kvw + 4096;
            float w00 = __ldg(vw + r0*64 + k0),       w01 = __ldg(vw + r0*64 + k0 + 1);
            float w10 = __ldg(vw + (r0+8)*64 + k0),   w11 = __ldg(vw + (r0+8)*64 + k0 + 1);
            float w20 = __ldg(vw + r0*64 + k0 + 8),   w21 = __ldg(vw + r0*64 + k0 + 9);
            float w30 = __ldg(vw + (r0+8)*64 + k0+8), w31 = __ldg(vw + (r0+8)*64 + k0 + 9);
            aWvh[cc][0] = pkbf(w00, w01); aWvl[cc][0] = pkbf(w00 - bf16f(w00), w01 - bf16f(w01));
            aWvh[cc][1] = pkbf(w10, w11); aWvl[cc][1] = pkbf(w10 - bf16f(w10), w11 - bf16f(w11));
            aWvh[cc][2] = pkbf(w20, w21); aWvl[cc][2] = pkbf(w20 - bf16f(w20), w21 - bf16f(w21));
            aWvh[cc][3] = pkbf(w30, w31); aWvl[cc][3] = pkbf(w30 - bf16f(w30), w31 - bf16f(w31));
        }
    }

    for (int tt = blockIdx.x; tt < NTILES; tt += gridDim.x){
        const int bb = tt >> 9;
        const size_t pxb = (size_t)(tt & 511) << 7;
        const float* gy = yin + (size_t)bb*64*HW + pxb;

        #pragma unroll
        for (int j = 0; j < 8; ++j){
            const int idx = tid + j*256;
            const int ch = idx & 63;
            const int px0 = (idx >> 6) << 2;
            float4 v = __ldg((const float4*)(gy + (size_t)ch*HW + px0));
            float o0 = __shfl_xor_sync(0xffffffffu, v.x, 1);
            float o1 = __shfl_xor_sync(0xffffffffu, v.y, 1);
            float o2 = __shfl_xor_sync(0xffffffffu, v.z, 1);
            float o3 = __shfl_xor_sync(0xffffffffu, v.w, 1);
            const int cp = ch >> 1;
            if (!(ch & 1)){
                float h0 = bf16f(v.x), h1 = bf16f(v.y);
                float p0 = bf16f(o0),  p1 = bf16f(o1);
                sYh[(px0    )*ROWW + cp] = pkbf(h0, p0);
                sYh[(px0 + 1)*ROWW + cp] = pkbf(h1, p1);
                sYl[(px0    )*ROWW + cp] = pkbf(v.x - h0, o0 - p0);
                sYl[(px0 + 1)*ROWW + cp] = pkbf(v.y - h1, o1 - p1);
            } else {
                float h2 = bf16f(v.z), h3 = bf16f(v.w);
                float p2 = bf16f(o2),  p3 = bf16f(o3);
                sYh[(px0 + 2)*ROWW + cp] = pkbf(p2, h2);
                sYh[(px0 + 3)*ROWW + cp] = pkbf(p3, h3);
                sYl[(px0 + 2)*ROWW + cp] = pkbf(o2 - p2, v.z - h2);
                sYl[(px0 + 3)*ROWW + cp] = pkbf(o3 - p3, v.w - h3);
            }
        }
        __syncthreads();

        const int pxw0 = (int)(pxb >> 1);
        #pragma unroll
        for (int nt = 0; nt < 8; ++nt){
            const int nb = nh*64 + nt*8;
            const int nrow = nb + grow;
            float ack[4] = {0.f, 0.f, 0.f, 0.f};
            float acv[4] = {0.f, 0.f, 0.f, 0.f};
            #pragma unroll
            for (int cc = 0; cc < 4; ++cc){
                unsigned bH[2], bL[2];
                const int w0 = nrow*ROWW + cc*8 + t;
                bH[0] = sYh[w0]; bH[1] = sYh[w0 + 4];
                bL[0] = sYl[w0]; bL[1] = sYl[w0 + 4];
                mma16816(ack, aWk[cc],  bH);
                mma16816(acv, aWvh[cc], bH);
                mma16816(acv, aWvh[cc], bL);
                mma16816(acv, aWvl[cc], bH);
            }
            const int ch = bb*64 + mb*16 + grow;
            const int pxp = pxw0 + (nb >> 1) + t;
            g_kvl[(size_t)ch*32768 + pxp]       = pkbf(ack[0], ack[1]);
            g_kvl[(size_t)(ch + 8)*32768 + pxp] = pkbf(ack[2], ack[3]);
            const size_t pxa = pxb + nb + 2*t;
            float2 v01; v01.x = acv[0]; v01.y = acv[1];
            float2 v23; v23.x = acv[2]; v23.y = acv[3];
            *(float2*)(g_kvh + (size_t)ch*HW + pxa)       = v01;
            *(float2*)(g_kvh + (size_t)(ch + 8)*HW + pxa) = v23;
        }
        __syncthreads();
    }
}

// ---------------- K2v: depthwise 3x3 for v planes (R13 proven) ----------------
__global__ void __launch_bounds__(256, 5) k2v_dw(const float* __restrict__ kvdw)
{
    const int b = blockIdx.z, c = blockIdx.y, band = blockIdx.x;
    const float* srcf = g_kvh + ((size_t)(b*64 + c))*HW;
    const float* w9 = kvdw + (64 + c)*9;

    float w[9];
    #pragma unroll
    for (int i = 0; i < 9; ++i) w[i] = __ldg(w9 + i);

    const int tid = threadIdx.x;
    const int rg = tid >> 5, lane = tid & 31;
    const int xx = lane << 3;
    const int y0 = band*32 + rg*4;

    float o[4][8];
    #pragma unroll
    for (int j = 0; j < 4; ++j)
        #pragma unroll
        for (int p = 0; p < 8; ++p) o[j][p] = 0.f;

    #pragma unroll
    for (int i = 0; i < 6; ++i){
        const int ys = y0 - 1 + i;
        const bool yok = (ys >= 0) && (ys <= 255);
        float c8[8];
        float4 a = make_float4(0.f,0.f,0.f,0.f), d = make_float4(0.f,0.f,0.f,0.f);
        if (yok){
            const float* row = srcf + ys*256 + xx;
            a = __ldg((const float4*)row);
            d = __ldg((const float4*)(row + 4));
        }
        c8[0]=a.x; c8[1]=a.y; c8[2]=a.z; c8[3]=a.w;
        c8[4]=d.x; c8[5]=d.y; c8[6]=d.z; c8[7]=d.w;
        float lv = __shfl_up_sync(0xffffffffu, c8[7], 1);
        float rv = __shfl_down_sync(0xffffffffu, c8[0], 1);
        if (lane == 0)  lv = 0.f;
        if (lane == 31) rv = 0.f;

        #pragma unroll
        for (int j = 0; j < 4; ++j){
            const int ky = i - j;
            if (ky >= 0 && ky < 3){
                const float wa = w[ky*3], wb = w[ky*3+1], wc = w[ky*3+2];
                o[j][0] += wa*lv + wb*c8[0] + wc*c8[1];
                #pragma unroll
                for (int p = 1; p < 7; ++p)
                    o[j][p] += wa*c8[p-1] + wb*c8[p] + wc*c8[p+1];
                o[j][7] += wa*c8[6] + wb*c8[7] + wc*rv;
            }
        }
    }

    const size_t obase = ((size_t)(b*64 + c))*HW + (size_t)y0*256 + xx;
    #pragma unroll
    for (int j = 0; j < 4; ++j){
        float4 a; a.x=o[j][0]; a.y=o[j][1]; a.z=o[j][2]; a.w=o[j][3];
        float4 d; d.x=o[j][4]; d.y=o[j][5]; d.z=o[j][6]; d.w=o[j][7];
        *(float4*)(g_v + obase + (size_t)j*256)     = a;
        *(float4*)(g_v + obase + (size_t)j*256 + 4) = d;
    }
}

// ---------------- K2qk: fused q/k dwconv + gram mma (R13 proven) ----------------
__global__ void __launch_bounds__(256) k2qk(
    const float* __restrict__ qdw, const float* __restrict__ kvdw)
{
    extern __shared__ unsigned smq[];
    unsigned* sQ = smq;
    unsigned* sK = smq + 16*QROW;
    float* sG = (float*)(smq + 32*QROW);

    const int band = blockIdx.x, h = blockIdx.y, b = blockIdx.z;
    const int tid = threadIdx.x, wid = tid >> 5, lane = tid & 31;
    const int y0 = band*4;
    const int xx = lane << 3;

    #pragma unroll
    for (int jj = 0; jj < 4; ++jj){
        const int job = wid*4 + jj;
        const int kindk = job & 1;
        const int c = job >> 1;
        const int cc = h*16 + c;
        const unsigned* srcb = (kindk ? g_kvl : g_qmb) + (((size_t)(b*64 + cc))*HW >> 1);
        const float* w9 = (kindk ? kvdw : qdw) + cc*9;
        float w[9];
        #pragma unroll
        for (int i = 0; i < 9; ++i) w[i] = __ldg(w9 + i);

        float o[4][8];
        #pragma unroll
        for (int j = 0; j < 4; ++j)
            #pragma unroll
            for (int p = 0; p < 8; ++p) o[j][p] = 0.f;

        #pragma unroll
        for (int i = 0; i < 6; ++i){
            const int ys = y0 - 1 + i;
            const bool yok = (ys >= 0) && (ys <= 255);
            uint4 u = make_uint4(0u,0u,0u,0u);
            if (yok) u = __ldg((const uint4*)(srcb + (ys << 7) + (xx >> 1)));
            float c8[8];
            c8[0]=bflo(u.x); c8[1]=bfhi(u.x); c8[2]=bflo(u.y); c8[3]=bfhi(u.y);
            c8[4]=bflo(u.z); c8[5]=bfhi(u.z); c8[6]=bflo(u.w); c8[7]=bfhi(u.w);
            float lv = __shfl_up_sync(0xffffffffu, c8[7], 1);
            float rv = __shfl_down_sync(0xffffffffu, c8[0], 1);
            if (lane == 0)  lv = 0.f;
            if (lane == 31) rv = 0.f;

            #pragma unroll
            for (int j = 0; j < 4; ++j){
                const int ky = i - j;
                if (ky >= 0 && ky < 3){
                    const float wa = w[ky*3], wb = w[ky*3+1], wc = w[ky*3+2];
                    o[j][0] += wa*lv + wb*c8[0] + wc*c8[1];
                    #pragma unroll
                    for (int p = 1; p < 7; ++p)
                        o[j][p] += wa*c8[p-1] + wb*c8[p] + wc*c8[p+1];
                    o[j][7] += wa*c8[6] + wb*c8[7] + wc*rv;
                }
            }
        }

        float s = 0.f;
        #pragma unroll
        for (int j = 0; j < 4; ++j)
            #pragma unroll
            for (int p = 0; p < 8; ++p) s += o[j][p]*o[j][p];
        #pragma unroll
        for (int off = 16; off; off >>= 1) s += __shfl_xor_sync(0xffffffffu, s, off);
        if (lane == 0)
            atomicAdd((kindk ? g_kss : g_qss) + b*64 + cc, s);

        unsigned* dst = (kindk ? sK : sQ) + c*QROW;
        #pragma unroll
        for (int j = 0; j < 4; ++j){
            uint4 u;
            u.x = pkbf(o[j][0], o[j][1]);
            u.y = pkbf(o[j][2], o[j][3]);
            u.z = pkbf(o[j][4], o[j][5]);
            u.w = pkbf(o[j][6], o[j][7]);
            *(uint4*)(dst + j*128 + lane*4) = u;
        }
    }
    __syncthreads();

    const int grow = lane >> 2, t = lane & 3;
    float c0[4] = {0.f, 0.f, 0.f, 0.f};
    float c1[4] = {0.f, 0.f, 0.f, 0.f};

    #pragma unroll
    for (int it = 0; it < 8; ++it){
        const int wb = wid*64 + it*8;
        unsigned a[4], b0[2], b1[2];
        a[0]  = sQ[grow*QROW      + wb + t];
        a[1]  = sQ[(grow+8)*QROW  + wb + t];
        a[2]  = sQ[grow*QROW      + wb + t + 4];
        a[3]  = sQ[(grow+8)*QROW  + wb + t + 4];
        b0[0] = sK[grow*QROW      + wb + t];
        b0[1] = sK[grow*QROW      + wb + t + 4];
        b1[0] = sK[(grow+8)*QROW  + wb + t];
        b1[1] = sK[(grow+8)*QROW  + wb + t + 4];
        mma16816(c0, a, b0);
        mma16816(c1, a, b1);
    }

    sG[wid*256 + grow*16          + t*2    ] = c0[0];
    sG[wid*256 + grow*16          + t*2 + 1] = c0[1];
    sG[wid*256 + (grow+8)*16      + t*2    ] = c0[2];
    sG[wid*256 + (grow+8)*16      + t*2 + 1] = c0[3];
    sG[wid*256 + grow*16 + 8      + t*2    ] = c1[0];
    sG[wid*256 + grow*16 + 8      + t*2 + 1] = c1[1];
    sG[wid*256 + (grow+8)*16 + 8  + t*2    ] = c1[2];
    sG[wid*256 + (grow+8)*16 + 8  + t*2 + 1] = c1[3];
    __syncthreads();

    float s = 0.f;
    #pragma unroll
    for (int w = 0; w < 8; ++w) s += sG[w*256 + tid];
    atomicAdd(g_gram + (b*4 + h)*256 + tid, s);
}

// ---------------- K4: split-bf16 mma; smem overlay (sM/sA reused as sVh/sVl) ----------------
// smem = 36864 B total; launch_bounds(256,4) -> 4 CTAs/SM
__global__ void __launch_bounds__(256, 4) k4_mma(
    float* __restrict__ out,
    const float* __restrict__ pjw, const float* __restrict__ temp)
{
    extern __shared__ unsigned smk[];
    // phase 1 (prologue): sM = floats[0..4096), sA = floats[4096..5120)
    float* sM = (float*)smk;
    float* sA = sM + 4096;
    // phase 2 (main loop): same region reused
    unsigned* sVh = smk;
    unsigned* sVl = smk + 128*ROWW;
    const int tid = threadIdx.x, wid = tid >> 5, lane = tid & 31;
    const int mb = wid & 3, nh = wid >> 2;
    const int grow = lane >> 2, t = lane & 3;
    const int b = blockIdx.x & 7;
    const int sub = blockIdx.x >> 3;
    const int bstride = gridDim.x >> 3;

    if (tid < 64){
        const int h = tid >> 4;
        const float tv = __ldg(temp + h);
        const float inq = tv / fmaxf(sqrtf(g_qss[b*64 + tid]), EPSN);
        const float* gr = g_gram + (b*4 + h)*256 + (tid & 15)*16;
        float l[16]; float mx = -1e30f;
        #pragma unroll
        for (int d = 0; d < 16; ++d){
            l[d] = gr[d] * inq / fmaxf(sqrtf(g_kss[b*64 + h*16 + d]), EPSN);
            mx = fmaxf(mx, l[d]);
        }
        float ssum = 0.f;
        #pragma unroll
        for (int d = 0; d < 16; ++d){ l[d] = __expf(l[d] - mx); ssum += l[d]; }
        const float inv = 1.f / ssum;
        #pragma unroll
        for (int d = 0; d < 16; ++d) sA[tid*16 + d] = l[d] * inv;
    }
    __syncthreads();
    for (int idx = tid; idx < 4096; idx += 256){
        const int o = idx >> 6, cd = idx & 63, h = cd >> 4, d = cd & 15;
        float s = 0.f;
        #pragma unroll
        for (int ci = 0; ci < 16; ++ci)
            s += __ldg(pjw + o*64 + h*16 + ci) * sA[(h*16 + ci)*16 + d];
        sM[idx] = s;
    }
    __syncthreads();

    unsigned aMh[4][4], aMl[4][4];
    {
        const int r0 = mb*16 + grow;
        #pragma unroll
        for (int cc = 0; cc < 4; ++cc){
            const int k0 = cc*16 + t*2;
            float w00 = sM[r0*64 + k0],       w01 = sM[r0*64 + k0 + 1];
            float w10 = sM[(r0+8)*64 + k0],   w11 = sM[(r0+8)*64 + k0 + 1];
            float w20 = sM[r0*64 + k0 + 8],   w21 = sM[r0*64 + k0 + 9];
            float w30 = sM[(r0+8)*64 + k0+8], w31 = sM[(r0+8)*64 + k0 + 9];
            aMh[cc][0] = pkbf(w00, w01); aMl[cc][0] = pkbf(w00 - bf16f(w00), w01 - bf16f(w01));
            aMh[cc][1] = pkbf(w10, w11); aMl[cc][1] = pkbf(w10 - bf16f(w10), w11 - bf16f(w11));
            aMh[cc][2] = pkbf(w20, w21); aMl[cc][2] = pkbf(w20 - bf16f(w20), w21 - bf16f(w21));
            aMh[cc][3] = pkbf(w30, w31); aMl[cc][3] = pkbf(w30 - bf16f(w30), w31 - bf16f(w31));
        }
    }
    __syncthreads();   // sM dead; region becomes sVh/sVl

    for (int tt = sub; tt < 512; tt += bstride){
        const size_t pxb = (size_t)tt << 7;
        const float* gv = g_v + (size_t)b*64*HW + pxb;

        #pragma unroll
        for (int j = 0; j < 8; ++j){
            const int idx = tid + j*256;
            const int ch = idx & 63;
            const int px0 = (idx >> 6) << 2;
            float4 v = __ldg((const float4*)(gv + (size_t)ch*HW + px0));
            float o0 = __shfl_xor_sync(0xffffffffu, v.x, 1);
            float o1 = __shfl_xor_sync(0xffffffffu, v.y, 1);
            float o2 = __shfl_xor_sync(0xffffffffu, v.z, 1);
            float o3 = __shfl_xor_sync(0xffffffffu, v.w, 1);
            const int cp = ch >> 1;
            if (!(ch & 1)){
                float h0 = bf16f(v.x), h1 = bf16f(v.y);
                float p0 = bf16f(o0),  p1 = bf16f(o1);
                sVh[(px0    )*ROWW + cp] = pkbf(h0, p0);
                sVh[(px0 + 1)*ROWW + cp] = pkbf(h1, p1);
                sVl[(px0    )*ROWW + cp] = pkbf(v.x - h0, o0 - p0);
                sVl[(px0 + 1)*ROWW + cp] = pkbf(v.y - h1, o1 - p1);
            } else {
                float h2 = bf16f(v.z), h3 = bf16f(v.w);
                float p2 = bf16f(o2),  p3 = bf16f(o3);
                sVh[(px0 + 2)*ROWW + cp] = pkbf(p2, h2);
                sVh[(px0 + 3)*ROWW + cp] = pkbf(p3, h3);
                sVl[(px0 + 2)*ROWW + cp] = pkbf(o2 - p2, v.z - h2);
                sVl[(px0 + 3)*ROWW + cp] = pkbf(o3 - p3, v.w - h3);
            }
        }
        __syncthreads();

        #pragma unroll
        for (int nt = 0; nt < 8; ++nt){
            const int nb = nh*64 + nt*8;
            const int nrow = nb + grow;
            float acv[4] = {0.f, 0.f, 0.f, 0.f};
            #pragma unroll
            for (int cc = 0; cc < 4; ++cc){
                unsigned bH[2], bL[2];
                const int w0 = nrow*ROWW + cc*8 + t;
                bH[0] = sVh[w0]; bH[1] = sVh[w0 + 4];
                bL[0] = sVl[w0]; bL[1] = sVl[w0 + 4];
                mma16816(acv, aMh[cc], bH);
                mma16816(acv, aMh[cc], bL);
                mma16816(acv, aMl[cc], bH);
            }
            const int ch = b*64 + mb*16 + grow;
            const size_t pxa = pxb + nb + 2*t;
            float2 v01; v01.x = acv[0]; v01.y = acv[1];
            float2 v23; v23.x = acv[2]; v23.y = acv[3];
            *(float2*)(out + (size_t)ch*HW + pxa)       = v01;
            *(float2*)(out + (size_t)(ch + 8)*HW + pxa) = v23;
        }
        __syncthreads();
    }
}

// ---------------- launch ----------------
extern "C" void kernel_launch(void* const* d_in, const int* in_sizes, int n_in,
                              void* d_out, int out_size)
{
    (void)in_sizes; (void)n_in; (void)out_size;
    const float* dg   = (const float*)d_in[0];
    const float* xin  = (const float*)d_in[1];
    const float* yin  = (const float*)d_in[2];
    const float* q1w  = (const float*)d_in[3];
    const float* q2w  = (const float*)d_in[4];
    const float* qdw  = (const float*)d_in[5];
    const float* kvw  = (const float*)d_in[6];
    const float* kvdw = (const float*)d_in[7];
    const float* pjw  = (const float*)d_in[8];
    const float* temp = (const float*)d_in[9];
    float* out = (float*)d_out;

    cudaFuncSetAttribute(k1a_mma, cudaFuncAttributeMaxDynamicSharedMemorySize, 36864);
    cudaFuncSetAttribute(k1b_mma, cudaFuncAttributeMaxDynamicSharedMemorySize, 36864);
    cudaFuncSetAttribute(k2qk,    cudaFuncAttributeMaxDynamicSharedMemorySize, 74240);
    cudaFuncSetAttribute(k4_mma,  cudaFuncAttributeMaxDynamicSharedMemorySize, 36864);

    k1a_mma<<<444, 256, 36864>>>(dg, xin, q1w, q2w);
    k1b_mma<<<444, 256, 36864>>>(yin, kvw);
    k2v_dw <<<dim3(8, 64, 8), 256>>>(kvdw);
    k2qk   <<<dim3(64, 4, 8), 256, 74240>>>(qdw, kvdw);
    k4_mma <<<592, 256, 36864>>>(out, pjw, temp);
}

// round 17
// speedup vs baseline: 1.0197x; 1.0091x over previous
#include <cuda_runtime.h>
#include <cuda_bf16.h>
#include <cstdint>

#define HW 65536
#define EPSN 1e-12f

typedef unsigned long long u64;

// ---------------- scratch (static device globals; no allocation) ----------------
__device__ unsigned g_qmb[16777216]; // [8][64][32768] bf16-pair qm
__device__ unsigned g_kvl[16777216]; // [8][64][32768] bf16-pair kvm low (k source)
__device__ float    g_kvh[33554432]; // [8][64][65536] f32 kvm high (v source)
__device__ float    g_v  [33554432]; // [8][64][65536] v after dwconv
__device__ float g_gram[8192];       // [8][4][16][16]
__device__ float g_qss[512];         // [8][64]
__device__ float g_kss[512];         // [8][64]

// ---------------- helpers ----------------
__device__ __forceinline__ float bflo(unsigned u){ return __int_as_float((int)(u << 16)); }
__device__ __forceinline__ float bfhi(unsigned u){ return __int_as_float((int)(u & 0xffff0000u)); }
__device__ __forceinline__ unsigned pkbf(float a, float b){
    __nv_bfloat162 p = __floats2bfloat162_rn(a, b);
    return *(unsigned*)&p;
}
__device__ __forceinline__ float bf16f(float x){
    return __bfloat162float(__float2bfloat16_rn(x));
}

// ---------------- warp mma (arch-generic bf16 HMMA) ----------------
__device__ __forceinline__ void mma16816(float* c, const unsigned* a, const unsigned* b){
    asm volatile("mma.sync.aligned.m16n8k16.row.col.f32.bf16.bf16.f32 "
        "{%0,%1,%2,%3}, {%4,%5,%6,%7}, {%8,%9}, {%0,%1,%2,%3};"
        : "+f"(c[0]), "+f"(c[1]), "+f"(c[2]), "+f"(c[3])
        : "r"(a[0]), "r"(a[1]), "r"(a[2]), "r"(a[3]), "r"(b[0]), "r"(b[1]));
}

#define NTILES 4096   // 128-px tiles over 8 batches x 65536 px
#define ROWW 36       // bf16 smem row stride in 32-bit words (72 bf16, padded)
#define QROW 516      // k2qk smem channel-row stride in words (512 + 4 pad)

// ---------------- K1a: q path via mma.sync bf16 + accumulator zeroing ----------------
__global__ void __launch_bounds__(256, 3) k1a_mma(
    const float* __restrict__ dg, const float* __restrict__ xin,
    const float* __restrict__ q1w, const float* __restrict__ q2w)
{
    extern __shared__ unsigned smk[];
    unsigned* sD = smk;
    unsigned* sX = smk + 128*ROWW;
    const int tid = threadIdx.x, wid = tid >> 5, lane = tid & 31;
    const int mb = wid & 3, nh = wid >> 2;
    const int grow = lane >> 2, t = lane & 3;

    // zero gram/qss/kss (k2qk is ordered after k1a via stream DAG)
    {
        const int idx = blockIdx.x*256 + tid;
        if (idx < 8192) g_gram[idx] = 0.f;
        else if (idx < 8704) g_qss[idx - 8192] = 0.f;
        else if (idx < 9216) g_kss[idx - 8704] = 0.f;
    }

    unsigned aW1[4][4], aW2[4][4];
    {
        const int r0 = mb*16 + grow;
        #pragma unroll
        for (int cc = 0; cc < 4; ++cc){
            const int k0 = cc*16 + t*2;
            aW1[cc][0] = pkbf(__ldg(q1w + r0*64 + k0),       __ldg(q1w + r0*64 + k0 + 1));
            aW1[cc][1] = pkbf(__ldg(q1w + (r0+8)*64 + k0),   __ldg(q1w + (r0+8)*64 + k0 + 1));
            aW1[cc][2] = pkbf(__ldg(q1w + r0*64 + k0 + 8),   __ldg(q1w + r0*64 + k0 + 9));
            aW1[cc][3] = pkbf(__ldg(q1w + (r0+8)*64 + k0+8), __ldg(q1w + (r0+8)*64 + k0 + 9));
            aW2[cc][0] = pkbf(__ldg(q2w + r0*64 + k0),       __ldg(q2w + r0*64 + k0 + 1));
            aW2[cc][1] = pkbf(__ldg(q2w + (r0+8)*64 + k0),   __ldg(q2w + (r0+8)*64 + k0 + 1));
            aW2[cc][2] = pkbf(__ldg(q2w + r0*64 + k0 + 8),   __ldg(q2w + r0*64 + k0 + 9));
            aW2[cc][3] = pkbf(__ldg(q2w + (r0+8)*64 + k0+8), __ldg(q2w + (r0+8)*64 + k0 + 9));
        }
    }

    auto cvt = [&](const float* gsrc, unsigned* sT){
        #pragma unroll
        for (int j = 0; j < 8; ++j){
            const int idx = tid + j*256;
            const int ch = idx & 63;
            const int px0 = (idx >> 6) << 2;
            float4 v = __ldg((const float4*)(gsrc + (size_t)ch*HW + px0));
            float o0 = __shfl_xor_sync(0xffffffffu, v.x, 1);
            float o1 = __shfl_xor_sync(0xffffffffu, v.y, 1);
            float o2 = __shfl_xor_sync(0xffffffffu, v.z, 1);
            float o3 = __shfl_xor_sync(0xffffffffu, v.w, 1);
            const int cp = ch >> 1;
            if (!(ch & 1)){
                sT[(px0    )*ROWW + cp] = pkbf(v.x, o0);
                sT[(px0 + 1)*ROWW + cp] = pkbf(v.y, o1);
            } else {
                sT[(px0 + 2)*ROWW + cp] = pkbf(o2, v.z);
                sT[(px0 + 3)*ROWW + cp] = pkbf(o3, v.w);
            }
        }
    };

    for (int tt = blockIdx.x; tt < NTILES; tt += gridDim.x){
        const int bb = tt >> 9;
        const size_t pxb = (size_t)(tt & 511) << 7;

        cvt(dg  + (size_t)bb*64*HW + pxb, sD);
        cvt(xin + (size_t)bb*64*HW + pxb, sX);
        __syncthreads();

        const int pxw0 = (int)(pxb >> 1);
        #pragma unroll
        for (int nt = 0; nt < 8; ++nt){
            const int nb = nh*64 + nt*8;
            const int nrow = nb + grow;
            float ac1[4] = {0.f, 0.f, 0.f, 0.f};
            float ac2[4] = {0.f, 0.f, 0.f, 0.f};
            #pragma unroll
            for (int cc = 0; cc < 4; ++cc){
                unsigned bD[2], bX[2];
                const int w0 = nrow*ROWW + cc*8 + t;
                bD[0] = sD[w0]; bD[1] = sD[w0 + 4];
                bX[0] = sX[w0]; bX[1] = sX[w0 + 4];
                mma16816(ac1, aW1[cc], bD);
                mma16816(ac2, aW2[cc], bX);
            }
            const int ch = bb*64 + mb*16 + grow;
            const int pxp = pxw0 + (nb >> 1) + t;
            g_qmb[(size_t)ch*32768 + pxp]       = pkbf(ac1[0]*ac2[0], ac1[1]*ac2[1]);
            g_qmb[(size_t)(ch + 8)*32768 + pxp] = pkbf(ac1[2]*ac2[2], ac1[3]*ac2[3]);
        }
        __syncthreads();
    }
}

// ---------------- K1b: kv GEMM via split-bf16 mma (R10/R12 proven) ----------------
__global__ void __launch_bounds__(256, 3) k1b_mma(
    const float* __restrict__ yin, const float* __restrict__ kvw)
{
    extern __shared__ unsigned smk[];
    unsigned* sYh = smk;
    unsigned* sYl = smk + 128*ROWW;
    const int tid = threadIdx.x, wid = tid >> 5, lane = tid & 31;
    const int mb = wid & 3, nh = wid >> 2;
    const int grow = lane >> 2, t = lane & 3;

    unsigned aWk[4][4], aWvh[4][4], aWvl[4][4];
    {
        const int r0 = mb*16 + grow;
        #pragma unroll
        for (int cc = 0; cc < 4; ++cc){
            const int k0 = cc*16 + t*2;
            aWk[cc][0] = pkbf(__ldg(kvw + r0*64 + k0),       __ldg(kvw + r0*64 + k0 + 1));
            aWk[cc][1] = pkbf(__ldg(kvw + (r0+8)*64 + k0),   __ldg(kvw + (r0+8)*64 + k0 + 1));
            aWk[cc][2] = pkbf(__ldg(kvw + r0*64 + k0 + 8),   __ldg(kvw + r0*64 + k0 + 9));
            aWk[cc][3] = pkbf(__ldg(kvw + (r0+8)*64 + k0+8), __ldg(kvw + (r0+8)*64 + k0 + 9));
            const float* vw = kvw + 4096;
            float w00 = __ldg(vw + r0*64 + k0),       w01 = __ldg(vw + r0*64 + k0 + 1);
            float w10 = __ldg(vw + (r0+8)*64 + k0),   w11 = __ldg(vw + (r0+8)*64 + k0 + 1);
            float w20 = __ldg(vw + r0*64 + k0 + 8),   w21 = __ldg(vw + r0*64 + k0 + 9);
            float w30 = __ldg(vw + (r0+8)*64 + k0+8), w31 = __ldg(vw + (r0+8)*64 + k0 + 9);
            aWvh[cc][0] = pkbf(w00, w01); aWvl[cc][0] = pkbf(w00 - bf16f(w00), w01 - bf16f(w01));
            aWvh[cc][1] = pkbf(w10, w11); aWvl[cc][1] = pkbf(w10 - bf16f(w10), w11 - bf16f(w11));
            aWvh[cc][2] = pkbf(w20, w21); aWvl[cc][2] = pkbf(w20 - bf16f(w20), w21 - bf16f(w21));
            aWvh[cc][3] = pkbf(w30, w31); aWvl[cc][3] = pkbf(w30 - bf16f(w30), w31 - bf16f(w31));
        }
    }

    for (int tt = blockIdx.x; tt < NTILES; tt += gridDim.x){
        const int bb = tt >> 9;
        const size_t pxb = (size_t)(tt & 511) << 7;
        const float* gy = yin + (size_t)bb*64*HW + pxb;

        #pragma unroll
        for (int j = 0; j < 8; ++j){
            const int idx = tid + j*256;
            const int ch = idx & 63;
            const int px0 = (idx >> 6) << 2;
            float4 v = __ldg((const float4*)(gy + (size_t)ch*HW + px0));
            float o0 = __shfl_xor_sync(0xffffffffu, v.x, 1);
            float o1 = __shfl_xor_sync(0xffffffffu, v.y, 1);
            float o2 = __shfl_xor_sync(0xffffffffu, v.z, 1);
            float o3 = __shfl_xor_sync(0xffffffffu, v.w, 1);
            const int cp = ch >> 1;
            if (!(ch & 1)){
                float h0 = bf16f(v.x), h1 = bf16f(v.y);
                float p0 = bf16f(o0),  p1 = bf16f(o1);
                sYh[(px0    )*ROWW + cp] = pkbf(h0, p0);
                sYh[(px0 + 1)*ROWW + cp] = pkbf(h1, p1);
                sYl[(px0    )*ROWW + cp] = pkbf(v.x - h0, o0 - p0);
                sYl[(px0 + 1)*ROWW + cp] = pkbf(v.y - h1, o1 - p1);
            } else {
                float h2 = bf16f(v.z), h3 = bf16f(v.w);
                float p2 = bf16f(o2),  p3 = bf16f(o3);
                sYh[(px0 + 2)*ROWW + cp] = pkbf(p2, h2);
                sYh[(px0 + 3)*ROWW + cp] = pkbf(p3, h3);
                sYl[(px0 + 2)*ROWW + cp] = pkbf(o2 - p2, v.z - h2);
                sYl[(px0 + 3)*ROWW + cp] = pkbf(o3 - p3, v.w - h3);
            }
        }
        __syncthreads();

        const int pxw0 = (int)(pxb >> 1);
        #pragma unroll
        for (int nt = 0; nt < 8; ++nt){
            const int nb = nh*64 + nt*8;
            const int nrow = nb + grow;
            float ack[4] = {0.f, 0.f, 0.f, 0.f};
            float acv[4] = {0.f, 0.f, 0.f, 0.f};
            #pragma unroll
            for (int cc = 0; cc < 4; ++cc){
                unsigned bH[2], bL[2];
                const int w0 = nrow*ROWW + cc*8 + t;
                bH[0] = sYh[w0]; bH[1] = sYh[w0 + 4];
                bL[0] = sYl[w0]; bL[1] = sYl[w0 + 4];
                mma16816(ack, aWk[cc],  bH);
                mma16816(acv, aWvh[cc], bH);
                mma16816(acv, aWvh[cc], bL);
                mma16816(acv, aWvl[cc], bH);
            }
            const int ch = bb*64 + mb*16 + grow;
            const int pxp = pxw0 + (nb >> 1) + t;
            g_kvl[(size_t)ch*32768 + pxp]       = pkbf(ack[0], ack[1]);
            g_kvl[(size_t)(ch + 8)*32768 + pxp] = pkbf(ack[2], ack[3]);
            const size_t pxa = pxb + nb + 2*t;
            float2 v01; v01.x = acv[0]; v01.y = acv[1];
            float2 v23; v23.x = acv[2]; v23.y = acv[3];
            *(float2*)(g_kvh + (size_t)ch*HW + pxa)       = v01;
            *(float2*)(g_kvh + (size_t)(ch + 8)*HW + pxa) = v23;
        }
        __syncthreads();
    }
}

// ---------------- K2v: depthwise 3x3 for v planes (R13 proven) ----------------
__global__ void __launch_bounds__(256, 5) k2v_dw(const float* __restrict__ kvdw)
{
    const int b = blockIdx.z, c = blockIdx.y, band = blockIdx.x;
    const float* srcf = g_kvh + ((size_t)(b*64 + c))*HW;
    const float* w9 = kvdw + (64 + c)*9;

    float w[9];
    #pragma unroll
    for (int i = 0; i < 9; ++i) w[i] = __ldg(w9 + i);

    const int tid = threadIdx.x;
    const int rg = tid >> 5, lane = tid & 31;
    const int xx = lane << 3;
    const int y0 = band*32 + rg*4;

    float o[4][8];
    #pragma unroll
    for (int j = 0; j < 4; ++j)
        #pragma unroll
        for (int p = 0; p < 8; ++p) o[j][p] = 0.f;

    #pragma unroll
    for (int i = 0; i < 6; ++i){
        const int ys = y0 - 1 + i;
        const bool yok = (ys >= 0) && (ys <= 255);
        float c8[8];
        float4 a = make_float4(0.f,0.f,0.f,0.f), d = make_float4(0.f,0.f,0.f,0.f);
        if (yok){
            const float* row = srcf + ys*256 + xx;
            a = __ldg((const float4*)row);
            d = __ldg((const float4*)(row + 4));
        }
        c8[0]=a.x; c8[1]=a.y; c8[2]=a.z; c8[3]=a.w;
        c8[4]=d.x; c8[5]=d.y; c8[6]=d.z; c8[7]=d.w;
        float lv = __shfl_up_sync(0xffffffffu, c8[7], 1);
        float rv = __shfl_down_sync(0xffffffffu, c8[0], 1);
        if (lane == 0)  lv = 0.f;
        if (lane == 31) rv = 0.f;

        #pragma unroll
        for (int j = 0; j < 4; ++j){
            const int ky = i - j;
            if (ky >= 0 && ky < 3){
                const float wa = w[ky*3], wb = w[ky*3+1], wc = w[ky*3+2];
                o[j][0] += wa*lv + wb*c8[0] + wc*c8[1];
                #pragma unroll
                for (int p = 1; p < 7; ++p)
                    o[j][p] += wa*c8[p-1] + wb*c8[p] + wc*c8[p+1];
                o[j][7] += wa*c8[6] + wb*c8[7] + wc*rv;
            }
        }
    }

    const size_t obase = ((size_t)(b*64 + c))*HW + (size_t)y0*256 + xx;
    #pragma unroll
    for (int j = 0; j < 4; ++j){
        float4 a; a.x=o[j][0]; a.y=o[j][1]; a.z=o[j][2]; a.w=o[j][3];
        float4 d; d.x=o[j][4]; d.y=o[j][5]; d.z=o[j][6]; d.w=o[j][7];
        *(float4*)(g_v + obase + (size_t)j*256)     = a;
        *(float4*)(g_v + obase + (size_t)j*256 + 4) = d;
    }
}

// ---------------- K2qk: fused q/k dwconv + gram mma (R13 proven) ----------------
__global__ void __launch_bounds__(256) k2qk(
    const float* __restrict__ qdw, const float* __restrict__ kvdw)
{
    extern __shared__ unsigned smq[];
    unsigned* sQ = smq;
    unsigned* sK = smq + 16*QROW;
    float* sG = (float*)(smq + 32*QROW);

    const int band = blockIdx.x, h = blockIdx.y, b = blockIdx.z;
    const int tid = threadIdx.x, wid = tid >> 5, lane = tid & 31;
    const int y0 = band*4;
    const int xx = lane << 3;

    #pragma unroll
    for (int jj = 0; jj < 4; ++jj){
        const int job = wid*4 + jj;
        const int kindk = job & 1;
        const int c = job >> 1;
        const int cc = h*16 + c;
        const unsigned* srcb = (kindk ? g_kvl : g_qmb) + (((size_t)(b*64 + cc))*HW >> 1);
        const float* w9 = (kindk ? kvdw : qdw) + cc*9;
        float w[9];
        #pragma unroll
        for (int i = 0; i < 9; ++i) w[i] = __ldg(w9 + i);

        float o[4][8];
        #pragma unroll
        for (int j = 0; j < 4; ++j)
            #pragma unroll
            for (int p = 0; p < 8; ++p) o[j][p] = 0.f;

        #pragma unroll
        for (int i = 0; i < 6; ++i){
            const int ys = y0 - 1 + i;
            const bool yok = (ys >= 0) && (ys <= 255);
            uint4 u = make_uint4(0u,0u,0u,0u);
            if (yok) u = __ldg((const uint4*)(srcb + (ys << 7) + (xx >> 1)));
            float c8[8];
            c8[0]=bflo(u.x); c8[1]=bfhi(u.x); c8[2]=bflo(u.y); c8[3]=bfhi(u.y);
            c8[4]=bflo(u.z); c8[5]=bfhi(u.z); c8[6]=bflo(u.w); c8[7]=bfhi(u.w);
            float lv = __shfl_up_sync(0xffffffffu, c8[7], 1);
            float rv = __shfl_down_sync(0xffffffffu, c8[0], 1);
            if (lane == 0)  lv = 0.f;
            if (lane == 31) rv = 0.f;

            #pragma unroll
            for (int j = 0; j < 4; ++j){
                const int ky = i - j;
                if (ky >= 0 && ky < 3){
                    const float wa = w[ky*3], wb = w[ky*3+1], wc = w[ky*3+2];
                    o[j][0] += wa*lv + wb*c8[0] + wc*c8[1];
                    #pragma unroll
                    for (int p = 1; p < 7; ++p)
                        o[j][p] += wa*c8[p-1] + wb*c8[p] + wc*c8[p+1];
                    o[j][7] += wa*c8[6] + wb*c8[7] + wc*rv;
                }
            }
        }

        float s = 0.f;
        #pragma unroll
        for (int j = 0; j < 4; ++j)
            #pragma unroll
            for (int p = 0; p < 8; ++p) s += o[j][p]*o[j][p];
        #pragma unroll
        for (int off = 16; off; off >>= 1) s += __shfl_xor_sync(0xffffffffu, s, off);
        if (lane == 0)
            atomicAdd((kindk ? g_kss : g_qss) + b*64 + cc, s);

        unsigned* dst = (kindk ? sK : sQ) + c*QROW;
        #pragma unroll
        for (int j = 0; j < 4; ++j){
            uint4 u;
            u.x = pkbf(o[j][0], o[j][1]);
            u.y = pkbf(o[j][2], o[j][3]);
            u.z = pkbf(o[j][4], o[j][5]);
            u.w = pkbf(o[j][6], o[j][7]);
            *(uint4*)(dst + j*128 + lane*4) = u;
        }
    }
    __syncthreads();

    const int grow = lane >> 2, t = lane & 3;
    float c0[4] = {0.f, 0.f, 0.f, 0.f};
    float c1[4] = {0.f, 0.f, 0.f, 0.f};

    #pragma unroll
    for (int it = 0; it < 8; ++it){
        const int wb = wid*64 + it*8;
        unsigned a[4], b0[2], b1[2];
        a[0]  = sQ[grow*QROW      + wb + t];
        a[1]  = sQ[(grow+8)*QROW  + wb + t];
        a[2]  = sQ[grow*QROW      + wb + t + 4];
        a[3]  = sQ[(grow+8)*QROW  + wb + t + 4];
        b0[0] = sK[grow*QROW      + wb + t];
        b0[1] = sK[grow*QROW      + wb + t + 4];
        b1[0] = sK[(grow+8)*QROW  + wb + t];
        b1[1] = sK[(grow+8)*QROW  + wb + t + 4];
        mma16816(c0, a, b0);
        mma16816(c1, a, b1);
    }

    sG[wid*256 + grow*16          + t*2    ] = c0[0];
    sG[wid*256 + grow*16          + t*2 + 1] = c0[1];
    sG[wid*256 + (grow+8)*16      + t*2    ] = c0[2];
    sG[wid*256 + (grow+8)*16      + t*2 + 1] = c0[3];
    sG[wid*256 + grow*16 + 8      + t*2    ] = c1[0];
    sG[wid*256 + grow*16 + 8      + t*2 + 1] = c1[1];
    sG[wid*256 + (grow+8)*16 + 8  + t*2    ] = c1[2];
    sG[wid*256 + (grow+8)*16 + 8  + t*2 + 1] = c1[3];
    __syncthreads();

    float s = 0.f;
    #pragma unroll
    for (int w = 0; w < 8; ++w) s += sG[w*256 + tid];
    atomicAdd(g_gram + (b*4 + h)*256 + tid, s);
}

// ---------------- K4: split-bf16 mma; smem overlay (R16) ----------------
__global__ void __launch_bounds__(256, 4) k4_mma(
    float* __restrict__ out,
    const float* __restrict__ pjw, const float* __restrict__ temp)
{
    extern __shared__ unsigned smk[];
    float* sM = (float*)smk;
    float* sA = sM + 4096;
    unsigned* sVh = smk;
    unsigned* sVl = smk + 128*ROWW;
    const int tid = threadIdx.x, wid = tid >> 5, lane = tid & 31;
    const int mb = wid & 3, nh = wid >> 2;
    const int grow = lane >> 2, t = lane & 3;
    const int b = blockIdx.x & 7;
    const int sub = blockIdx.x >> 3;
    const int bstride = gridDim.x >> 3;

    if (tid < 64){
        const int h = tid >> 4;
        const float tv = __ldg(temp + h);
        const float inq = tv / fmaxf(sqrtf(g_qss[b*64 + tid]), EPSN);
        const float* gr = g_gram + (b*4 + h)*256 + (tid & 15)*16;
        float l[16]; float mx = -1e30f;
        #pragma unroll
        for (int d = 0; d < 16; ++d){
            l[d] = gr[d] * inq / fmaxf(sqrtf(g_kss[b*64 + h*16 + d]), EPSN);
            mx = fmaxf(mx, l[d]);
        }
        float ssum = 0.f;
        #pragma unroll
        for (int d = 0; d < 16; ++d){ l[d] = __expf(l[d] - mx); ssum += l[d]; }
        const float inv = 1.f / ssum;
        #pragma unroll
        for (int d = 0; d < 16; ++d) sA[tid*16 + d] = l[d] * inv;
    }
    __syncthreads();
    for (int idx = tid; idx < 4096; idx += 256){
        const int o = idx >> 6, cd = idx & 63, h = cd >> 4, d = cd & 15;
        float s = 0.f;
        #pragma unroll
        for (int ci = 0; ci < 16; ++ci)
            s += __ldg(pjw + o*64 + h*16 + ci) * sA[(h*16 + ci)*16 + d];
        sM[idx] = s;
    }
    __syncthreads();

    unsigned aMh[4][4], aMl[4][4];
    {
        const int r0 = mb*16 + grow;
        #pragma unroll
        for (int cc = 0; cc < 4; ++cc){
            const int k0 = cc*16 + t*2;
            float w00 = sM[r0*64 + k0],       w01 = sM[r0*64 + k0 + 1];
            float w10 = sM[(r0+8)*64 + k0],   w11 = sM[(r0+8)*64 + k0 + 1];
            float w20 = sM[r0*64 + k0 + 8],   w21 = sM[r0*64 + k0 + 9];
            float w30 = sM[(r0+8)*64 + k0+8], w31 = sM[(r0+8)*64 + k0 + 9];
            aMh[cc][0] = pkbf(w00, w01); aMl[cc][0] = pkbf(w00 - bf16f(w00), w01 - bf16f(w01));
            aMh[cc][1] = pkbf(w10, w11); aMl[cc][1] = pkbf(w10 - bf16f(w10), w11 - bf16f(w11));
            aMh[cc][2] = pkbf(w20, w21); aMl[cc][2] = pkbf(w20 - bf16f(w20), w21 - bf16f(w21));
            aMh[cc][3] = pkbf(w30, w31); aMl[cc][3] = pkbf(w30 - bf16f(w30), w31 - bf16f(w31));
        }
    }
    __syncthreads();

    for (int tt = sub; tt < 512; tt += bstride){
        const size_t pxb = (size_t)tt << 7;
        const float* gv = g_v + (size_t)b*64*HW + pxb;

        #pragma unroll
        for (int j = 0; j < 8; ++j){
            const int idx = tid + j*256;
            const int ch = idx & 63;
            const int px0 = (idx >> 6) << 2;
            float4 v = __ldg((const float4*)(gv + (size_t)ch*HW + px0));
            float o0 = __shfl_xor_sync(0xffffffffu, v.x, 1);
            float o1 = __shfl_xor_sync(0xffffffffu, v.y, 1);
            float o2 = __shfl_xor_sync(0xffffffffu, v.z, 1);
            float o3 = __shfl_xor_sync(0xffffffffu, v.w, 1);
            const int cp = ch >> 1;
            if (!(ch & 1)){
                float h0 = bf16f(v.x), h1 = bf16f(v.y);
                float p0 = bf16f(o0),  p1 = bf16f(o1);
                sVh[(px0    )*ROWW + cp] = pkbf(h0, p0);
                sVh[(px0 + 1)*ROWW + cp] = pkbf(h1, p1);
                sVl[(px0    )*ROWW + cp] = pkbf(v.x - h0, o0 - p0);
                sVl[(px0 + 1)*ROWW + cp] = pkbf(v.y - h1, o1 - p1);
            } else {
                float h2 = bf16f(v.z), h3 = bf16f(v.w);
                float p2 = bf16f(o2),  p3 = bf16f(o3);
                sVh[(px0 + 2)*ROWW + cp] = pkbf(p2, h2);
                sVh[(px0 + 3)*ROWW + cp] = pkbf(p3, h3);
                sVl[(px0 + 2)*ROWW + cp] = pkbf(o2 - p2, v.z - h2);
                sVl[(px0 + 3)*ROWW + cp] = pkbf(o3 - p3, v.w - h3);
            }
        }
        __syncthreads();

        #pragma unroll
        for (int nt = 0; nt < 8; ++nt){
            const int nb = nh*64 + nt*8;
            const int nrow = nb + grow;
            float acv[4] = {0.f, 0.f, 0.f, 0.f};
            #pragma unroll
            for (int cc = 0; cc < 4; ++cc){
                unsigned bH[2], bL[2];
                const int w0 = nrow*ROWW + cc*8 + t;
                bH[0] = sVh[w0]; bH[1] = sVh[w0 + 4];
                bL[0] = sVl[w0]; bL[1] = sVl[w0 + 4];
                mma16816(acv, aMh[cc], bH);
                mma16816(acv, aMh[cc], bL);
                mma16816(acv, aMl[cc], bH);
            }
            const int ch = b*64 + mb*16 + grow;
            const size_t pxa = pxb + nb + 2*t;
            float2 v01; v01.x = acv[0]; v01.y = acv[1];
            float2 v23; v23.x = acv[2]; v23.y = acv[3];
            *(float2*)(out + (size_t)ch*HW + pxa)       = v01;
            *(float2*)(out + (size_t)(ch + 8)*HW + pxa) = v23;
        }
        __syncthreads();
    }
}

// ---------------- launch: forked-stream DAG for kernel-level overlap ----------------
extern "C" void kernel_launch(void* const* d_in, const int* in_sizes, int n_in,
                              void* d_out, int out_size)
{
    (void)in_sizes; (void)n_in; (void)out_size;
    const float* dg   = (const float*)d_in[0];
    const float* xin  = (const float*)d_in[1];
    const float* yin  = (const float*)d_in[2];
    const float* q1w  = (const float*)d_in[3];
    const float* q2w  = (const float*)d_in[4];
    const float* qdw  = (const float*)d_in[5];
    const float* kvw  = (const float*)d_in[6];
    const float* kvdw = (const float*)d_in[7];
    const float* pjw  = (const float*)d_in[8];
    const float* temp = (const float*)d_in[9];
    float* out = (float*)d_out;

    cudaFuncSetAttribute(k1a_mma, cudaFuncAttributeMaxDynamicSharedMemorySize, 36864);
    cudaFuncSetAttribute(k1b_mma, cudaFuncAttributeMaxDynamicSharedMemorySize, 36864);
    cudaFuncSetAttribute(k2qk,    cudaFuncAttributeMaxDynamicSharedMemorySize, 74240);
    cudaFuncSetAttribute(k4_mma,  cudaFuncAttributeMaxDynamicSharedMemorySize, 36864);

    // fork a side stream off the (captured) legacy stream
    cudaStream_t s1;
    cudaEvent_t ev0, ev1, ev2;
    cudaStreamCreateWithFlags(&s1, cudaStreamNonBlocking);
    cudaEventCreateWithFlags(&ev0, cudaEventDisableTiming);
    cudaEventCreateWithFlags(&ev1, cudaEventDisableTiming);
    cudaEventCreateWithFlags(&ev2, cudaEventDisableTiming);

    cudaEventRecord(ev0, 0);
    cudaStreamWaitEvent(s1, ev0, 0);

    // s0: q path; s1: kv path (independent)
    k1a_mma<<<444, 256, 36864, 0>>>(dg, xin, q1w, q2w);
    k1b_mma<<<444, 256, 36864, s1>>>(yin, kvw);

    // s1 continues with v dwconv (needs only kvh from k1b)
    cudaEventRecord(ev1, s1);              // k1b done (kvl ready for k2qk)
    k2v_dw<<<dim3(8, 64, 8), 256, 0, s1>>>(kvdw);
    cudaEventRecord(ev2, s1);              // k2v done (g_v ready)

    // s0: gram kernel needs qmb (s0) + kvl (ev1); overlaps with k2v on s1
    cudaStreamWaitEvent(0, ev1, 0);
    k2qk<<<dim3(64, 4, 8), 256, 74240, 0>>>(qdw, kvdw);

    // s0: k4 needs gram (s0) + g_v (ev2) — joins s1 back into s0
    cudaStreamWaitEvent(0, ev2, 0);
    k4_mma<<<592, 256, 36864, 0>>>(out, pjw, temp);
    // streams/events intentionally not destroyed during capture (leaked; ~2 calls total)
}